// round 1
// baseline (speedup 1.0000x reference)
#include <cuda_runtime.h>
#include <math.h>
#include <stdint.h>

// Problem constants
#define B_   8
#define SQ_  2048
#define SKV_ 2048
#define D_   1024

// Scratch (device globals: allocation-free per harness rules)
__device__ float g_Q [(size_t)B_ * SQ_  * D_  ];  // 67 MB
__device__ float g_K [(size_t)B_ * SKV_ * D_  ];  // 67 MB
__device__ float g_Vt[(size_t)B_ * D_   * SKV_];  // 67 MB (V transposed per batch: [b][d][k])
__device__ float g_S [(size_t)B_ * SQ_  * SKV_];  // 134 MB (scores / probs)

// ---------------------------------------------------------------------------
// NT GEMM: C[m,n] = sum_k A[m,k] * B[n,k] (+ bias[n])
// A: [M,K] row-major, B: [N,K] row-major. Tile 128x128x8, 256 threads, 8x8 frags,
// double-buffered smem.
// TRANSC == 1: write C transposed per batch-of-rows: gm -> (bb, s), store
//              C[(bb*N + gn)*batchRows + s]   (used to produce V^T)
// ---------------------------------------------------------------------------
#define BM 128
#define BN 128
#define BK 8
#define TM 8
#define TN 8

template <int TRANSC>
__global__ __launch_bounds__(256)
void gemm_nt(const float* __restrict__ A, const float* __restrict__ Bm,
             float* __restrict__ C, const float* __restrict__ bias,
             int M, int N, int K,
             long long sA, long long sB, long long sC, int batchRows)
{
    A  += (long long)blockIdx.z * sA;
    Bm += (long long)blockIdx.z * sB;
    C  += (long long)blockIdx.z * sC;

    __shared__ float As[2][BK][BM];
    __shared__ float Bs[2][BK][BN];

    const int tid  = threadIdx.x;
    const int tx   = tid & 15;        // n-fragment index (0..15)
    const int ty   = tid >> 4;        // m-fragment index (0..15)
    const int lrow = tid >> 1;        // 0..127 : tile row loaded by this thread
    const int lcol = (tid & 1) * 4;   // 0 or 4 : starting k within BK

    const int m0 = blockIdx.y * BM;
    const int n0 = blockIdx.x * BN;

    const float* Aptr = A  + (long long)(m0 + lrow) * K + lcol;
    const float* Bptr = Bm + (long long)(n0 + lrow) * K + lcol;

    float acc[TM][TN];
#pragma unroll
    for (int i = 0; i < TM; ++i)
#pragma unroll
        for (int j = 0; j < TN; ++j) acc[i][j] = 0.0f;

    // preload tile 0
    {
        float4 a4 = *reinterpret_cast<const float4*>(Aptr);
        float4 b4 = *reinterpret_cast<const float4*>(Bptr);
        As[0][lcol + 0][lrow] = a4.x;
        As[0][lcol + 1][lrow] = a4.y;
        As[0][lcol + 2][lrow] = a4.z;
        As[0][lcol + 3][lrow] = a4.w;
        Bs[0][lcol + 0][lrow] = b4.x;
        Bs[0][lcol + 1][lrow] = b4.y;
        Bs[0][lcol + 2][lrow] = b4.z;
        Bs[0][lcol + 3][lrow] = b4.w;
    }
    __syncthreads();

    const int nTiles = K / BK;
    for (int t = 0; t < nTiles; ++t) {
        const int cur = t & 1;
        const int nxt = cur ^ 1;

        float4 a4n, b4n;
        const bool more = (t + 1 < nTiles);
        if (more) {
            a4n = *reinterpret_cast<const float4*>(Aptr + (t + 1) * BK);
            b4n = *reinterpret_cast<const float4*>(Bptr + (t + 1) * BK);
        }

        const float (*AsC)[BM] = As[cur];
        const float (*BsC)[BN] = Bs[cur];
#pragma unroll
        for (int k = 0; k < BK; ++k) {
            float a[TM], b[TN];
#pragma unroll
            for (int i = 0; i < TM; ++i) a[i] = AsC[k][ty * TM + i];
#pragma unroll
            for (int j = 0; j < TN; ++j) b[j] = BsC[k][tx * TN + j];
#pragma unroll
            for (int i = 0; i < TM; ++i)
#pragma unroll
                for (int j = 0; j < TN; ++j)
                    acc[i][j] += a[i] * b[j];
        }

        if (more) {
            As[nxt][lcol + 0][lrow] = a4n.x;
            As[nxt][lcol + 1][lrow] = a4n.y;
            As[nxt][lcol + 2][lrow] = a4n.z;
            As[nxt][lcol + 3][lrow] = a4n.w;
            Bs[nxt][lcol + 0][lrow] = b4n.x;
            Bs[nxt][lcol + 1][lrow] = b4n.y;
            Bs[nxt][lcol + 2][lrow] = b4n.z;
            Bs[nxt][lcol + 3][lrow] = b4n.w;
            __syncthreads();
        }
    }

    // epilogue
#pragma unroll
    for (int i = 0; i < TM; ++i) {
        const int gm = m0 + ty * TM + i;
#pragma unroll
        for (int j = 0; j < TN; ++j) {
            const int gn = n0 + tx * TN + j;
            float v = acc[i][j];
            if (bias) v += bias[gn];
            if (TRANSC == 0) {
                C[(long long)gm * N + gn] = v;
            } else {
                const int bb = gm / batchRows;
                const int s  = gm % batchRows;
                C[((long long)bb * N + gn) * batchRows + s] = v;
            }
        }
    }
}

// ---------------------------------------------------------------------------
// Row softmax over 2048 columns. One block (256 threads) per row.
// ---------------------------------------------------------------------------
__global__ __launch_bounds__(256)
void softmax_rows(float* __restrict__ S)
{
    const int COLS = SKV_;
    float* p = S + (size_t)blockIdx.x * COLS;
    const int tid  = threadIdx.x;
    const int lane = tid & 31;
    const int warp = tid >> 5;

    __shared__ float red[8];

    float v[8];
    float m = -INFINITY;
#pragma unroll
    for (int i = 0; i < 8; ++i) {
        v[i] = p[tid + i * 256];
        m = fmaxf(m, v[i]);
    }
#pragma unroll
    for (int o = 16; o > 0; o >>= 1) m = fmaxf(m, __shfl_xor_sync(0xffffffffu, m, o));
    if (lane == 0) red[warp] = m;
    __syncthreads();
    float mrow = red[0];
#pragma unroll
    for (int w = 1; w < 8; ++w) mrow = fmaxf(mrow, red[w]);
    __syncthreads();

    float s = 0.0f;
#pragma unroll
    for (int i = 0; i < 8; ++i) {
        v[i] = expf(v[i] - mrow);
        s += v[i];
    }
#pragma unroll
    for (int o = 16; o > 0; o >>= 1) s += __shfl_xor_sync(0xffffffffu, s, o);
    if (lane == 0) red[warp] = s;
    __syncthreads();
    float srow = 0.0f;
#pragma unroll
    for (int w = 0; w < 8; ++w) srow += red[w];
    const float inv = 1.0f / srow;

#pragma unroll
    for (int i = 0; i < 8; ++i) p[tid + i * 256] = v[i] * inv;
}

// ---------------------------------------------------------------------------
// Launch
// ---------------------------------------------------------------------------
extern "C" void kernel_launch(void* const* d_in, const int* in_sizes, int n_in,
                              void* d_out, int out_size)
{
    const float* target     = (const float*)d_in[0];
    const float* non_target = (const float*)d_in[1];
    const float* Wq = (const float*)d_in[2];
    const float* bq = (const float*)d_in[3];
    const float* Wk = (const float*)d_in[4];
    const float* bk = (const float*)d_in[5];
    const float* Wv = (const float*)d_in[6];
    const float* bv = (const float*)d_in[7];
    float* out = (float*)d_out;

    float *Q, *K, *Vt, *S;
    cudaGetSymbolAddress((void**)&Q,  g_Q);
    cudaGetSymbolAddress((void**)&K,  g_K);
    cudaGetSymbolAddress((void**)&Vt, g_Vt);
    cudaGetSymbolAddress((void**)&S,  g_S);

    const dim3 blk(256);

    // Projections: rows = B*S (batch folded into M), N = D, K = D
    gemm_nt<0><<<dim3(D_ / BN, (B_ * SQ_) / BM, 1), blk>>>(
        target, Wq, Q, bq, B_ * SQ_, D_, D_, 0, 0, 0, 0);
    gemm_nt<0><<<dim3(D_ / BN, (B_ * SKV_) / BM, 1), blk>>>(
        non_target, Wk, K, bk, B_ * SKV_, D_, D_, 0, 0, 0, 0);
    // V projection, written transposed per batch: Vt[b][d][k] = v[b][k][d]
    gemm_nt<1><<<dim3(D_ / BN, (B_ * SKV_) / BM, 1), blk>>>(
        non_target, Wv, Vt, bv, B_ * SKV_, D_, D_, 0, 0, 0, SKV_);

    // Scores: S[b] = Q[b] @ K[b]^T   [SQ x SKV], inner D
    gemm_nt<0><<<dim3(SKV_ / BN, SQ_ / BM, B_), blk>>>(
        Q, K, S, nullptr, SQ_, SKV_, D_,
        (long long)SQ_ * D_, (long long)SKV_ * D_, (long long)SQ_ * SKV_, 0);

    // Softmax rows (in place)
    softmax_rows<<<B_ * SQ_, blk>>>(S);

    // O[b] = P[b] @ V[b]  ==  P[b] (SQ x SKV) @ Vt[b] (D x SKV)^T   -> [SQ x D]
    gemm_nt<0><<<dim3(D_ / BN, SQ_ / BM, B_), blk>>>(
        S, Vt, out, nullptr, SQ_, D_, SKV_,
        (long long)SQ_ * SKV_, (long long)D_ * SKV_, (long long)SQ_ * D_, 0);
}

// round 3
// speedup vs baseline: 2.4453x; 2.4453x over previous
#include <cuda_runtime.h>
#include <cuda_bf16.h>
#include <math.h>
#include <stdint.h>

#define B_   8
#define SQ_  2048
#define SKV_ 2048
#define D_   1024

typedef __nv_bfloat16 bf16;

// ---------------------------------------------------------------------------
// Device scratch (allocation-free per harness rules)
// ---------------------------------------------------------------------------
__device__ bf16 g_tH [16777216], g_tL [16777216];   // target split
__device__ bf16 g_nH [16777216], g_nL [16777216];   // non_target split
__device__ bf16 g_WqH[ 1048576], g_WqL[ 1048576];
__device__ bf16 g_WkH[ 1048576], g_WkL[ 1048576];
__device__ bf16 g_WvH[ 1048576], g_WvL[ 1048576];
__device__ bf16 g_QH [16777216], g_QL [16777216];
__device__ bf16 g_KH [16777216], g_KL [16777216];
__device__ bf16 g_VtH[16777216], g_VtL[16777216];   // V^T per batch [b][d][kv]
__device__ float g_S [33554432];                    // scores fp32
__device__ bf16 g_PH [33554432], g_PL [33554432];   // probs split

__device__ __forceinline__ uint32_t smem_u32(const void* p) {
    uint32_t a;
    asm("{ .reg .u64 t; cvta.to.shared.u64 t, %1; cvt.u32.u64 %0, t; }" : "=r"(a) : "l"(p));
    return a;
}

// ---------------------------------------------------------------------------
// Warp-MMA primitives (sm_80 baseline features; safe under compute_103)
// ---------------------------------------------------------------------------
#define LDSM4(r, ad) \
    asm volatile("ldmatrix.sync.aligned.m8n8.x4.shared.b16 {%0,%1,%2,%3}, [%4];" \
        : "=r"((r)[0]), "=r"((r)[1]), "=r"((r)[2]), "=r"((r)[3]) : "r"(ad))

#define LDSM2(r, ad) \
    asm volatile("ldmatrix.sync.aligned.m8n8.x2.shared.b16 {%0,%1}, [%2];" \
        : "=r"((r)[0]), "=r"((r)[1]) : "r"(ad))

#define MMA_BF16(c, a, b) \
    asm volatile("mma.sync.aligned.m16n8k16.row.col.f32.bf16.bf16.f32 " \
        "{%0,%1,%2,%3}, {%4,%5,%6,%7}, {%8,%9}, {%0,%1,%2,%3};" \
        : "+f"((c)[0]), "+f"((c)[1]), "+f"((c)[2]), "+f"((c)[3]) \
        : "r"((a)[0]), "r"((a)[1]), "r"((a)[2]), "r"((a)[3]), \
          "r"((b)[0]), "r"((b)[1]))

#define CP_ASYNC16(dst, src) \
    asm volatile("cp.async.cg.shared.global [%0], [%1], 16;" :: "r"(dst), "l"(src))
#define CP_COMMIT()  asm volatile("cp.async.commit_group;" ::: "memory")
#define CP_WAIT1()   asm volatile("cp.async.wait_group 1;" ::: "memory")

// ---------------------------------------------------------------------------
// Split-bf16 NT GEMM: C[m,n] = sum_k (Ah+Al)[m,k]*(Bh+Bl)[n,k] ~= hh+hl+lh (+bias)
// A,B row-major, leading dim K. CTA tile 128x128, BK=32, 8 warps (2m x 4n),
// 3-stage cp.async pipeline. Padded SMEM rows (80B stride, conflict-free ldmatrix).
// EPI: 0 = fp32 C, 1 = split-bf16 + bias, 2 = split-bf16 transposed + bias
// ---------------------------------------------------------------------------
#define STAGES 3
#define ROWB  80                       // 32 bf16 (64B) + 16B pad
#define PLANE (128 * ROWB)             // 10240 B
#define STAGE_BYTES (4 * PLANE)        // 40960 B
#define SMEM_BYTES (STAGES * STAGE_BYTES)  // 122880 B

template <int EPI>
__global__ void __launch_bounds__(256, 1)
mma_nt(const bf16* __restrict__ Ah, const bf16* __restrict__ Al,
       const bf16* __restrict__ Bh, const bf16* __restrict__ Bl,
       void* __restrict__ C0, void* __restrict__ C1,
       const float* __restrict__ bias,
       int K, int ldC,
       long long sA, long long sB, long long sC, int batchRows)
{
    extern __shared__ __align__(128) char smem[];
    const uint32_t sbase = smem_u32(smem);
    const int tid  = threadIdx.x;
    const int lane = tid & 31;
    const int wid  = tid >> 5;
    const int wm   = wid & 1;      // 2 warps along m
    const int wn   = wid >> 1;     // 4 warps along n

    Ah += (long long)blockIdx.z * sA;  Al += (long long)blockIdx.z * sA;
    Bh += (long long)blockIdx.z * sB;  Bl += (long long)blockIdx.z * sB;

    const int m0 = blockIdx.y * 128;
    const int n0 = blockIdx.x * 128;
    const int nChunks = K >> 5;

    // --- cp.async one K-chunk (4 planes x 128 rows x 64B) into a stage -----
    auto issue = [&](int t) {
        if (t < nChunks) {
            const int stage = t % STAGES;
            const int k0 = t << 5;
#pragma unroll
            for (int i = 0; i < 8; ++i) {
                const int idx = tid + (i << 8);       // 0..2047
                const int c = idx & 3;                // 16B chunk within row
                const int r = (idx >> 2) & 127;       // tile row
                const int p = idx >> 9;               // plane
                const bf16* src;
                if      (p == 0) src = Ah + (size_t)(m0 + r) * K + k0 + c * 8;
                else if (p == 1) src = Al + (size_t)(m0 + r) * K + k0 + c * 8;
                else if (p == 2) src = Bh + (size_t)(n0 + r) * K + k0 + c * 8;
                else             src = Bl + (size_t)(n0 + r) * K + k0 + c * 8;
                const uint32_t dst = sbase + stage * STAGE_BYTES + p * PLANE
                                   + r * ROWB + c * 16;
                CP_ASYNC16(dst, src);
            }
        }
        CP_COMMIT();
    };

    float acc[4][4][4];
#pragma unroll
    for (int mi = 0; mi < 4; ++mi)
#pragma unroll
        for (int ni = 0; ni < 4; ++ni)
#pragma unroll
            for (int e = 0; e < 4; ++e) acc[mi][ni][e] = 0.0f;

    issue(0);
    issue(1);

    for (int t = 0; t < nChunks; ++t) {
        CP_WAIT1();
        __syncthreads();
        issue(t + 2);   // fills the stage freed by iteration t-1

        const uint32_t st = sbase + (t % STAGES) * STAGE_BYTES;
#pragma unroll
        for (int ks = 0; ks < 2; ++ks) {
            uint32_t ah[4][4], al[4][4], bh[4][2], bl[4][2];

            const uint32_t akoff = (uint32_t)((ks << 5) + ((lane >> 4) << 4));
            const uint32_t arow  = (uint32_t)(wm * 64 + (lane & 15));
#pragma unroll
            for (int mi = 0; mi < 4; ++mi) {
                const uint32_t ad = st + (arow + mi * 16) * ROWB + akoff;
                LDSM4(ah[mi], ad);
                LDSM4(al[mi], ad + PLANE);
            }
            const uint32_t bkoff = (uint32_t)((ks << 5) + (((lane >> 3) & 1) << 4));
            const uint32_t brow  = (uint32_t)(wn * 32 + (lane & 7));
#pragma unroll
            for (int ni = 0; ni < 4; ++ni) {
                const uint32_t bd = st + 2 * PLANE + (brow + ni * 8) * ROWB + bkoff;
                LDSM2(bh[ni], bd);
                LDSM2(bl[ni], bd + PLANE);
            }
#pragma unroll
            for (int mi = 0; mi < 4; ++mi)
#pragma unroll
                for (int ni = 0; ni < 4; ++ni) {
                    MMA_BF16(acc[mi][ni], ah[mi], bh[ni]);
                    MMA_BF16(acc[mi][ni], ah[mi], bl[ni]);
                    MMA_BF16(acc[mi][ni], al[mi], bh[ni]);
                }
        }
    }

    // ---------------------------- epilogue ---------------------------------
    const int qr = lane >> 2;          // 0..7
    const int qc = (lane & 3) << 1;    // 0,2,4,6

#pragma unroll
    for (int mi = 0; mi < 4; ++mi) {
        const int gm0 = m0 + wm * 64 + mi * 16 + qr;   // row, and gm0+8
#pragma unroll
        for (int ni = 0; ni < 4; ++ni) {
            const int gn = n0 + wn * 32 + ni * 8 + qc;
            float v00 = acc[mi][ni][0], v01 = acc[mi][ni][1];
            float v10 = acc[mi][ni][2], v11 = acc[mi][ni][3];

            if (EPI == 0) {
                float* C = (float*)C0 + (long long)blockIdx.z * sC;
                *reinterpret_cast<float2*>(C + (size_t)gm0 * ldC + gn)
                    = make_float2(v00, v01);
                *reinterpret_cast<float2*>(C + (size_t)(gm0 + 8) * ldC + gn)
                    = make_float2(v10, v11);
            } else {
                const float b0v = bias[gn], b1v = bias[gn + 1];
                v00 += b0v; v01 += b1v; v10 += b0v; v11 += b1v;
                bf16 h00 = __float2bfloat16(v00);
                bf16 h01 = __float2bfloat16(v01);
                bf16 h10 = __float2bfloat16(v10);
                bf16 h11 = __float2bfloat16(v11);
                bf16 l00 = __float2bfloat16(v00 - __bfloat162float(h00));
                bf16 l01 = __float2bfloat16(v01 - __bfloat162float(h01));
                bf16 l10 = __float2bfloat16(v10 - __bfloat162float(h10));
                bf16 l11 = __float2bfloat16(v11 - __bfloat162float(h11));
                bf16* CH = (bf16*)C0;
                bf16* CL = (bf16*)C1;
                if (EPI == 1) {
                    __nv_bfloat162 hp0; hp0.x = h00; hp0.y = h01;
                    __nv_bfloat162 hp1; hp1.x = h10; hp1.y = h11;
                    __nv_bfloat162 lp0; lp0.x = l00; lp0.y = l01;
                    __nv_bfloat162 lp1; lp1.x = l10; lp1.y = l11;
                    *reinterpret_cast<__nv_bfloat162*>(CH + (size_t)gm0 * ldC + gn) = hp0;
                    *reinterpret_cast<__nv_bfloat162*>(CH + (size_t)(gm0 + 8) * ldC + gn) = hp1;
                    *reinterpret_cast<__nv_bfloat162*>(CL + (size_t)gm0 * ldC + gn) = lp0;
                    *reinterpret_cast<__nv_bfloat162*>(CL + (size_t)(gm0 + 8) * ldC + gn) = lp1;
                } else {  // EPI == 2: V^T scatter  (gm -> (bb, s), col-major per batch)
                    const int bb = gm0 / batchRows;
                    const int s0 = gm0 - bb * batchRows;
                    const size_t colbase = ((size_t)bb * ldC + gn) * (size_t)batchRows;
                    CH[colbase + s0]                  = h00;
                    CH[colbase + batchRows + s0]      = h01;
                    CH[colbase + s0 + 8]              = h10;
                    CH[colbase + batchRows + s0 + 8]  = h11;
                    CL[colbase + s0]                  = l00;
                    CL[colbase + batchRows + s0]      = l01;
                    CL[colbase + s0 + 8]              = l10;
                    CL[colbase + batchRows + s0 + 8]  = l11;
                }
            }
        }
    }
}

// ---------------------------------------------------------------------------
// fp32 -> (bf16 hi, bf16 lo)
// ---------------------------------------------------------------------------
__global__ void split_f32(const float* __restrict__ x, bf16* __restrict__ h,
                          bf16* __restrict__ l, int n)
{
    for (int i = blockIdx.x * blockDim.x + threadIdx.x; i < n; i += gridDim.x * blockDim.x) {
        float v = x[i];
        bf16 hh = __float2bfloat16(v);
        h[i] = hh;
        l[i] = __float2bfloat16(v - __bfloat162float(hh));
    }
}

// ---------------------------------------------------------------------------
// Row softmax (2048 cols) fused with split-bf16 conversion of P
// ---------------------------------------------------------------------------
__global__ __launch_bounds__(256)
void softmax_split(const float* __restrict__ S, bf16* __restrict__ Ph, bf16* __restrict__ Pl)
{
    const float* p = S + (size_t)blockIdx.x * SKV_;
    const int tid = threadIdx.x;
    const int lane = tid & 31;
    const int warp = tid >> 5;
    __shared__ float red[8];

    float v[8];
    float m = -INFINITY;
#pragma unroll
    for (int i = 0; i < 8; ++i) { v[i] = p[tid + i * 256]; m = fmaxf(m, v[i]); }
#pragma unroll
    for (int o = 16; o > 0; o >>= 1) m = fmaxf(m, __shfl_xor_sync(0xffffffffu, m, o));
    if (lane == 0) red[warp] = m;
    __syncthreads();
    float mrow = red[0];
#pragma unroll
    for (int w = 1; w < 8; ++w) mrow = fmaxf(mrow, red[w]);
    __syncthreads();

    float s = 0.0f;
#pragma unroll
    for (int i = 0; i < 8; ++i) { v[i] = expf(v[i] - mrow); s += v[i]; }
#pragma unroll
    for (int o = 16; o > 0; o >>= 1) s += __shfl_xor_sync(0xffffffffu, s, o);
    if (lane == 0) red[warp] = s;
    __syncthreads();
    float srow = 0.0f;
#pragma unroll
    for (int w = 0; w < 8; ++w) srow += red[w];
    const float inv = 1.0f / srow;

    const size_t base = (size_t)blockIdx.x * SKV_;
#pragma unroll
    for (int i = 0; i < 8; ++i) {
        float pv = v[i] * inv;
        bf16 h = __float2bfloat16(pv);
        Ph[base + tid + i * 256] = h;
        Pl[base + tid + i * 256] = __float2bfloat16(pv - __bfloat162float(h));
    }
}

// ---------------------------------------------------------------------------
// Launch
// ---------------------------------------------------------------------------
extern "C" void kernel_launch(void* const* d_in, const int* in_sizes, int n_in,
                              void* d_out, int out_size)
{
    const float* target     = (const float*)d_in[0];
    const float* non_target = (const float*)d_in[1];
    const float* Wq = (const float*)d_in[2];
    const float* bq = (const float*)d_in[3];
    const float* Wk = (const float*)d_in[4];
    const float* bk = (const float*)d_in[5];
    const float* Wv = (const float*)d_in[6];
    const float* bv = (const float*)d_in[7];
    float* out = (float*)d_out;

    bf16 *tH, *tL, *nH, *nL, *WqH, *WqL, *WkH, *WkL, *WvH, *WvL;
    bf16 *QH, *QL, *KH, *KL, *VtH, *VtL, *PH, *PL;
    float* S;
    cudaGetSymbolAddress((void**)&tH,  g_tH);  cudaGetSymbolAddress((void**)&tL,  g_tL);
    cudaGetSymbolAddress((void**)&nH,  g_nH);  cudaGetSymbolAddress((void**)&nL,  g_nL);
    cudaGetSymbolAddress((void**)&WqH, g_WqH); cudaGetSymbolAddress((void**)&WqL, g_WqL);
    cudaGetSymbolAddress((void**)&WkH, g_WkH); cudaGetSymbolAddress((void**)&WkL, g_WkL);
    cudaGetSymbolAddress((void**)&WvH, g_WvH); cudaGetSymbolAddress((void**)&WvL, g_WvL);
    cudaGetSymbolAddress((void**)&QH,  g_QH);  cudaGetSymbolAddress((void**)&QL,  g_QL);
    cudaGetSymbolAddress((void**)&KH,  g_KH);  cudaGetSymbolAddress((void**)&KL,  g_KL);
    cudaGetSymbolAddress((void**)&VtH, g_VtH); cudaGetSymbolAddress((void**)&VtL, g_VtL);
    cudaGetSymbolAddress((void**)&PH,  g_PH);  cudaGetSymbolAddress((void**)&PL,  g_PL);
    cudaGetSymbolAddress((void**)&S,   g_S);

    cudaFuncSetAttribute(mma_nt<0>, cudaFuncAttributeMaxDynamicSharedMemorySize, SMEM_BYTES);
    cudaFuncSetAttribute(mma_nt<1>, cudaFuncAttributeMaxDynamicSharedMemorySize, SMEM_BYTES);
    cudaFuncSetAttribute(mma_nt<2>, cudaFuncAttributeMaxDynamicSharedMemorySize, SMEM_BYTES);

    const dim3 blk(256);

    // input conversions
    split_f32<<<8192, blk>>>(target,     tH, tL, B_ * SQ_ * D_);
    split_f32<<<8192, blk>>>(non_target, nH, nL, B_ * SKV_ * D_);
    split_f32<<<1024, blk>>>(Wq, WqH, WqL, D_ * D_);
    split_f32<<<1024, blk>>>(Wk, WkH, WkL, D_ * D_);
    split_f32<<<1024, blk>>>(Wv, WvH, WvL, D_ * D_);

    // Q/K/V projections (M = B*S folded, N = D, K = D)
    mma_nt<1><<<dim3(8, 128, 1), blk, SMEM_BYTES>>>(
        tH, tL, WqH, WqL, QH, QL, bq, D_, D_, 0, 0, 0, 0);
    mma_nt<1><<<dim3(8, 128, 1), blk, SMEM_BYTES>>>(
        nH, nL, WkH, WkL, KH, KL, bk, D_, D_, 0, 0, 0, 0);
    mma_nt<2><<<dim3(8, 128, 1), blk, SMEM_BYTES>>>(
        nH, nL, WvH, WvL, VtH, VtL, bv, D_, D_, 0, 0, 0, SKV_);

    // S[b] = Q[b] @ K[b]^T
    mma_nt<0><<<dim3(16, 16, 8), blk, SMEM_BYTES>>>(
        QH, QL, KH, KL, S, nullptr, nullptr, D_, SKV_,
        (long long)SQ_ * D_, (long long)SKV_ * D_, (long long)SQ_ * SKV_, 0);

    // softmax + split conversion of P
    softmax_split<<<B_ * SQ_, blk>>>(S, PH, PL);

    // O[b] = P[b] @ Vt[b]^T
    mma_nt<0><<<dim3(8, 16, 8), blk, SMEM_BYTES>>>(
        PH, PL, VtH, VtL, out, nullptr, nullptr, SKV_, D_,
        (long long)SQ_ * SKV_, (long long)D_ * SKV_, (long long)SQ_ * D_, 0);
}

// round 4
// speedup vs baseline: 2.5085x; 1.0258x over previous
#include <cuda_runtime.h>
#include <cuda_bf16.h>
#include <math.h>
#include <stdint.h>

#define B_   8
#define SQ_  2048
#define SKV_ 2048
#define D_   1024

typedef __nv_bfloat16 bf16;

// ---------------------------------------------------------------------------
// Device scratch (allocation-free per harness rules)
// ---------------------------------------------------------------------------
__device__ bf16 g_tH [16777216], g_tL [16777216];   // target split
__device__ bf16 g_nH [16777216], g_nL [16777216];   // non_target split
__device__ bf16 g_WqH[ 1048576], g_WqL[ 1048576];
__device__ bf16 g_WkH[ 1048576], g_WkL[ 1048576];
__device__ bf16 g_WvH[ 1048576], g_WvL[ 1048576];
__device__ bf16 g_QH [16777216], g_QL [16777216];
__device__ bf16 g_KH [16777216], g_KL [16777216];
__device__ bf16 g_VtH[16777216], g_VtL[16777216];   // V^T per batch [b][d][kv]
__device__ float g_S [33554432];                    // scores fp32
__device__ bf16 g_PH [33554432], g_PL [33554432];   // probs split

__device__ __forceinline__ uint32_t smem_u32(const void* p) {
    uint32_t a;
    asm("{ .reg .u64 t; cvta.to.shared.u64 t, %1; cvt.u32.u64 %0, t; }" : "=r"(a) : "l"(p));
    return a;
}

// ---------------------------------------------------------------------------
// Warp-MMA primitives (sm_80 baseline; safe under compute_103)
// ---------------------------------------------------------------------------
#define LDSM4(r, ad) \
    asm volatile("ldmatrix.sync.aligned.m8n8.x4.shared.b16 {%0,%1,%2,%3}, [%4];" \
        : "=r"((r)[0]), "=r"((r)[1]), "=r"((r)[2]), "=r"((r)[3]) : "r"(ad))

#define MMA_BF16(c, a, b) \
    asm volatile("mma.sync.aligned.m16n8k16.row.col.f32.bf16.bf16.f32 " \
        "{%0,%1,%2,%3}, {%4,%5,%6,%7}, {%8,%9}, {%0,%1,%2,%3};" \
        : "+f"((c)[0]), "+f"((c)[1]), "+f"((c)[2]), "+f"((c)[3]) \
        : "r"((a)[0]), "r"((a)[1]), "r"((a)[2]), "r"((a)[3]), \
          "r"((b)[0]), "r"((b)[1]))

#define CP_ASYNC16(dst, src) \
    asm volatile("cp.async.cg.shared.global [%0], [%1], 16;" :: "r"(dst), "l"(src))
#define CP_COMMIT()  asm volatile("cp.async.commit_group;" ::: "memory")
#define CP_WAIT2()   asm volatile("cp.async.wait_group 2;" ::: "memory")

// ---------------------------------------------------------------------------
// Split-bf16 NT GEMM: C[m,n] = sum_k (Ah+Al)[m,k]*(Bh+Bl)[n,k] ~= hh+hl+lh (+bias)
// CTA tile 128x128, BK=32, 8 warps (2m x 4n), 4-stage cp.async pipeline.
// EPI: 0 = fp32 C, 1 = split-bf16 + bias, 2 = split-bf16 transposed + bias
// ---------------------------------------------------------------------------
#define STAGES 4
#define ROWB  80                       // 32 bf16 (64B) + 16B pad
#define PLANE (128 * ROWB)             // 10240 B
#define STAGE_BYTES (4 * PLANE)        // 40960 B
#define SMEM_BYTES (STAGES * STAGE_BYTES)  // 163840 B

template <int EPI>
__global__ void __launch_bounds__(256, 1)
mma_nt(const bf16* __restrict__ Ah, const bf16* __restrict__ Al,
       const bf16* __restrict__ Bh, const bf16* __restrict__ Bl,
       void* __restrict__ C0, void* __restrict__ C1,
       const float* __restrict__ bias,
       int K, int ldC,
       long long sA, long long sB, long long sC, int batchRows)
{
    extern __shared__ __align__(128) char smem[];
    const uint32_t sbase = smem_u32(smem);
    const int tid  = threadIdx.x;
    const int lane = tid & 31;
    const int wid  = tid >> 5;
    const int wm   = wid & 1;      // 2 warps along m
    const int wn   = wid >> 1;     // 4 warps along n

    Ah += (long long)blockIdx.z * sA;  Al += (long long)blockIdx.z * sA;
    Bh += (long long)blockIdx.z * sB;  Bl += (long long)blockIdx.z * sB;

    const int m0 = blockIdx.y * 128;
    const int n0 = blockIdx.x * 128;
    const int nChunks = K >> 5;

    // --- cp.async one K-chunk (4 planes x 128 rows x 64B) into a stage -----
    auto issue = [&](int t) {
        if (t < nChunks) {
            const int stage = t & (STAGES - 1);
            const int k0 = t << 5;
#pragma unroll
            for (int i = 0; i < 8; ++i) {
                const int idx = tid + (i << 8);       // 0..2047
                const int c = idx & 3;                // 16B chunk within row
                const int r = (idx >> 2) & 127;       // tile row
                const int p = idx >> 9;               // plane
                const bf16* src;
                if      (p == 0) src = Ah + (size_t)(m0 + r) * K + k0 + c * 8;
                else if (p == 1) src = Al + (size_t)(m0 + r) * K + k0 + c * 8;
                else if (p == 2) src = Bh + (size_t)(n0 + r) * K + k0 + c * 8;
                else             src = Bl + (size_t)(n0 + r) * K + k0 + c * 8;
                const uint32_t dst = sbase + stage * STAGE_BYTES + p * PLANE
                                   + r * ROWB + c * 16;
                CP_ASYNC16(dst, src);
            }
        }
        CP_COMMIT();
    };

    float acc[4][4][4];
#pragma unroll
    for (int mi = 0; mi < 4; ++mi)
#pragma unroll
        for (int ni = 0; ni < 4; ++ni)
#pragma unroll
            for (int e = 0; e < 4; ++e) acc[mi][ni][e] = 0.0f;

    issue(0);
    issue(1);
    issue(2);

    for (int t = 0; t < nChunks; ++t) {
        CP_WAIT2();          // group t complete; t+1, t+2 still in flight
        __syncthreads();
        issue(t + 3);        // fills stage freed after iteration t-1

        const uint32_t st = sbase + (t & (STAGES - 1)) * STAGE_BYTES;
#pragma unroll
        for (int ks = 0; ks < 2; ++ks) {
            uint32_t ah[4][4], al[4][4], bh[2][4], bl[2][4];

            // A fragments: ldmatrix.x4 per 16-row block (hi + lo planes)
            const uint32_t akoff = (uint32_t)((ks << 5) + ((lane >> 4) << 4));
            const uint32_t arow  = (uint32_t)(wm * 64 + (lane & 15));
#pragma unroll
            for (int mi = 0; mi < 4; ++mi) {
                const uint32_t ad = st + (arow + mi * 16) * ROWB + akoff;
                LDSM4(ah[mi], ad);
                LDSM4(al[mi], ad + PLANE);
            }
            // B fragments: one ldmatrix.x4 covers 16 n-rows x 16 k
            //   m0: rows 0-7 k0-7 | m1: rows 0-7 k8-15 | m2: rows 8-15 k0-7 | m3: rows 8-15 k8-15
            const uint32_t bkoff = (uint32_t)((ks << 5) + (((lane >> 3) & 1) << 4));
            const uint32_t brow  = (uint32_t)(wn * 32 + (lane & 7) + ((lane >> 4) << 3));
#pragma unroll
            for (int np = 0; np < 2; ++np) {   // pairs of n-frags
                const uint32_t bd = st + 2 * PLANE + (brow + np * 16) * ROWB + bkoff;
                LDSM4(bh[np], bd);
                LDSM4(bl[np], bd + PLANE);
            }
#pragma unroll
            for (int mi = 0; mi < 4; ++mi)
#pragma unroll
                for (int ni = 0; ni < 4; ++ni) {
                    const uint32_t* bhp = &bh[ni >> 1][(ni & 1) << 1];
                    const uint32_t* blp = &bl[ni >> 1][(ni & 1) << 1];
                    MMA_BF16(acc[mi][ni], ah[mi], bhp);
                    MMA_BF16(acc[mi][ni], ah[mi], blp);
                    MMA_BF16(acc[mi][ni], al[mi], bhp);
                }
        }
    }

    // ---------------------------- epilogue ---------------------------------
    const int qr = lane >> 2;          // 0..7
    const int qc = (lane & 3) << 1;    // 0,2,4,6

#pragma unroll
    for (int mi = 0; mi < 4; ++mi) {
        const int gm0 = m0 + wm * 64 + mi * 16 + qr;   // row, and gm0+8
#pragma unroll
        for (int ni = 0; ni < 4; ++ni) {
            const int gn = n0 + wn * 32 + ni * 8 + qc;
            float v00 = acc[mi][ni][0], v01 = acc[mi][ni][1];
            float v10 = acc[mi][ni][2], v11 = acc[mi][ni][3];

            if (EPI == 0) {
                float* C = (float*)C0 + (long long)blockIdx.z * sC;
                *reinterpret_cast<float2*>(C + (size_t)gm0 * ldC + gn)
                    = make_float2(v00, v01);
                *reinterpret_cast<float2*>(C + (size_t)(gm0 + 8) * ldC + gn)
                    = make_float2(v10, v11);
            } else {
                const float b0v = bias[gn], b1v = bias[gn + 1];
                v00 += b0v; v01 += b1v; v10 += b0v; v11 += b1v;
                bf16 h00 = __float2bfloat16(v00);
                bf16 h01 = __float2bfloat16(v01);
                bf16 h10 = __float2bfloat16(v10);
                bf16 h11 = __float2bfloat16(v11);
                bf16 l00 = __float2bfloat16(v00 - __bfloat162float(h00));
                bf16 l01 = __float2bfloat16(v01 - __bfloat162float(h01));
                bf16 l10 = __float2bfloat16(v10 - __bfloat162float(h10));
                bf16 l11 = __float2bfloat16(v11 - __bfloat162float(h11));
                bf16* CH = (bf16*)C0;
                bf16* CL = (bf16*)C1;
                if (EPI == 1) {
                    __nv_bfloat162 hp0; hp0.x = h00; hp0.y = h01;
                    __nv_bfloat162 hp1; hp1.x = h10; hp1.y = h11;
                    __nv_bfloat162 lp0; lp0.x = l00; lp0.y = l01;
                    __nv_bfloat162 lp1; lp1.x = l10; lp1.y = l11;
                    *reinterpret_cast<__nv_bfloat162*>(CH + (size_t)gm0 * ldC + gn) = hp0;
                    *reinterpret_cast<__nv_bfloat162*>(CH + (size_t)(gm0 + 8) * ldC + gn) = hp1;
                    *reinterpret_cast<__nv_bfloat162*>(CL + (size_t)gm0 * ldC + gn) = lp0;
                    *reinterpret_cast<__nv_bfloat162*>(CL + (size_t)(gm0 + 8) * ldC + gn) = lp1;
                } else {  // EPI == 2: V^T scatter  (gm -> (bb, s), col-major per batch)
                    const int bb = gm0 / batchRows;
                    const int s0 = gm0 - bb * batchRows;
                    const size_t colbase = ((size_t)bb * ldC + gn) * (size_t)batchRows;
                    CH[colbase + s0]                  = h00;
                    CH[colbase + batchRows + s0]      = h01;
                    CH[colbase + s0 + 8]              = h10;
                    CH[colbase + batchRows + s0 + 8]  = h11;
                    CL[colbase + s0]                  = l00;
                    CL[colbase + batchRows + s0]      = l01;
                    CL[colbase + s0 + 8]              = l10;
                    CL[colbase + batchRows + s0 + 8]  = l11;
                }
            }
        }
    }
}

// ---------------------------------------------------------------------------
// fp32 -> (bf16 hi, bf16 lo), vectorized: 8 elements / thread
// ---------------------------------------------------------------------------
__global__ void split_f32(const float* __restrict__ x, bf16* __restrict__ h,
                          bf16* __restrict__ l, int n)
{
    const int n8 = n >> 3;
    for (int i = blockIdx.x * blockDim.x + threadIdx.x; i < n8; i += gridDim.x * blockDim.x) {
        const float4 a = reinterpret_cast<const float4*>(x)[2 * i];
        const float4 b = reinterpret_cast<const float4*>(x)[2 * i + 1];
        float v[8] = { a.x, a.y, a.z, a.w, b.x, b.y, b.z, b.w };
        __align__(16) bf16 hb[8];
        __align__(16) bf16 lb[8];
#pragma unroll
        for (int j = 0; j < 8; ++j) {
            bf16 hh = __float2bfloat16(v[j]);
            hb[j] = hh;
            lb[j] = __float2bfloat16(v[j] - __bfloat162float(hh));
        }
        reinterpret_cast<uint4*>(h)[i] = *reinterpret_cast<uint4*>(hb);
        reinterpret_cast<uint4*>(l)[i] = *reinterpret_cast<uint4*>(lb);
    }
}

// ---------------------------------------------------------------------------
// Row softmax (2048 cols) fused with split-bf16 conversion; vectorized
// ---------------------------------------------------------------------------
__global__ __launch_bounds__(256)
void softmax_split(const float* __restrict__ S, bf16* __restrict__ Ph, bf16* __restrict__ Pl)
{
    const size_t base = (size_t)blockIdx.x * SKV_;
    const float* p = S + base;
    const int tid = threadIdx.x;
    const int lane = tid & 31;
    const int warp = tid >> 5;
    __shared__ float red[8];

    const float4 a = reinterpret_cast<const float4*>(p)[2 * tid];
    const float4 b = reinterpret_cast<const float4*>(p)[2 * tid + 1];
    float v[8] = { a.x, a.y, a.z, a.w, b.x, b.y, b.z, b.w };

    float m = -INFINITY;
#pragma unroll
    for (int i = 0; i < 8; ++i) m = fmaxf(m, v[i]);
#pragma unroll
    for (int o = 16; o > 0; o >>= 1) m = fmaxf(m, __shfl_xor_sync(0xffffffffu, m, o));
    if (lane == 0) red[warp] = m;
    __syncthreads();
    float mrow = red[0];
#pragma unroll
    for (int w = 1; w < 8; ++w) mrow = fmaxf(mrow, red[w]);
    __syncthreads();

    float s = 0.0f;
#pragma unroll
    for (int i = 0; i < 8; ++i) { v[i] = expf(v[i] - mrow); s += v[i]; }
#pragma unroll
    for (int o = 16; o > 0; o >>= 1) s += __shfl_xor_sync(0xffffffffu, s, o);
    if (lane == 0) red[warp] = s;
    __syncthreads();
    float srow = 0.0f;
#pragma unroll
    for (int w = 0; w < 8; ++w) srow += red[w];
    const float inv = 1.0f / srow;

    __align__(16) bf16 hb[8];
    __align__(16) bf16 lb[8];
#pragma unroll
    for (int i = 0; i < 8; ++i) {
        float pv = v[i] * inv;
        bf16 h = __float2bfloat16(pv);
        hb[i] = h;
        lb[i] = __float2bfloat16(pv - __bfloat162float(h));
    }
    reinterpret_cast<uint4*>(Ph + base)[tid] = *reinterpret_cast<uint4*>(hb);
    reinterpret_cast<uint4*>(Pl + base)[tid] = *reinterpret_cast<uint4*>(lb);
}

// ---------------------------------------------------------------------------
// Launch
// ---------------------------------------------------------------------------
extern "C" void kernel_launch(void* const* d_in, const int* in_sizes, int n_in,
                              void* d_out, int out_size)
{
    const float* target     = (const float*)d_in[0];
    const float* non_target = (const float*)d_in[1];
    const float* Wq = (const float*)d_in[2];
    const float* bq = (const float*)d_in[3];
    const float* Wk = (const float*)d_in[4];
    const float* bk = (const float*)d_in[5];
    const float* Wv = (const float*)d_in[6];
    const float* bv = (const float*)d_in[7];
    float* out = (float*)d_out;

    bf16 *tH, *tL, *nH, *nL, *WqH, *WqL, *WkH, *WkL, *WvH, *WvL;
    bf16 *QH, *QL, *KH, *KL, *VtH, *VtL, *PH, *PL;
    float* S;
    cudaGetSymbolAddress((void**)&tH,  g_tH);  cudaGetSymbolAddress((void**)&tL,  g_tL);
    cudaGetSymbolAddress((void**)&nH,  g_nH);  cudaGetSymbolAddress((void**)&nL,  g_nL);
    cudaGetSymbolAddress((void**)&WqH, g_WqH); cudaGetSymbolAddress((void**)&WqL, g_WqL);
    cudaGetSymbolAddress((void**)&WkH, g_WkH); cudaGetSymbolAddress((void**)&WkL, g_WkL);
    cudaGetSymbolAddress((void**)&WvH, g_WvH); cudaGetSymbolAddress((void**)&WvL, g_WvL);
    cudaGetSymbolAddress((void**)&QH,  g_QH);  cudaGetSymbolAddress((void**)&QL,  g_QL);
    cudaGetSymbolAddress((void**)&KH,  g_KH);  cudaGetSymbolAddress((void**)&KL,  g_KL);
    cudaGetSymbolAddress((void**)&VtH, g_VtH); cudaGetSymbolAddress((void**)&VtL, g_VtL);
    cudaGetSymbolAddress((void**)&PH,  g_PH);  cudaGetSymbolAddress((void**)&PL,  g_PL);
    cudaGetSymbolAddress((void**)&S,   g_S);

    cudaFuncSetAttribute(mma_nt<0>, cudaFuncAttributeMaxDynamicSharedMemorySize, SMEM_BYTES);
    cudaFuncSetAttribute(mma_nt<1>, cudaFuncAttributeMaxDynamicSharedMemorySize, SMEM_BYTES);
    cudaFuncSetAttribute(mma_nt<2>, cudaFuncAttributeMaxDynamicSharedMemorySize, SMEM_BYTES);

    const dim3 blk(256);

    // input conversions (8 elems/thread, exact cover)
    split_f32<<<8192, blk>>>(target,     tH, tL, B_ * SQ_ * D_);
    split_f32<<<8192, blk>>>(non_target, nH, nL, B_ * SKV_ * D_);
    split_f32<<<512,  blk>>>(Wq, WqH, WqL, D_ * D_);
    split_f32<<<512,  blk>>>(Wk, WkH, WkL, D_ * D_);
    split_f32<<<512,  blk>>>(Wv, WvH, WvL, D_ * D_);

    // Q/K/V projections (M = B*S folded, N = D, K = D)
    mma_nt<1><<<dim3(8, 128, 1), blk, SMEM_BYTES>>>(
        tH, tL, WqH, WqL, QH, QL, bq, D_, D_, 0, 0, 0, 0);
    mma_nt<1><<<dim3(8, 128, 1), blk, SMEM_BYTES>>>(
        nH, nL, WkH, WkL, KH, KL, bk, D_, D_, 0, 0, 0, 0);
    mma_nt<2><<<dim3(8, 128, 1), blk, SMEM_BYTES>>>(
        nH, nL, WvH, WvL, VtH, VtL, bv, D_, D_, 0, 0, 0, SKV_);

    // S[b] = Q[b] @ K[b]^T
    mma_nt<0><<<dim3(16, 16, 8), blk, SMEM_BYTES>>>(
        QH, QL, KH, KL, S, nullptr, nullptr, D_, SKV_,
        (long long)SQ_ * D_, (long long)SKV_ * D_, (long long)SQ_ * SKV_, 0);

    // softmax + split conversion of P
    softmax_split<<<B_ * SQ_, blk>>>(S, PH, PL);

    // O[b] = P[b] @ Vt[b]^T
    mma_nt<0><<<dim3(8, 16, 8), blk, SMEM_BYTES>>>(
        PH, PL, VtH, VtL, out, nullptr, nullptr, SKV_, D_,
        (long long)SQ_ * SKV_, (long long)D_ * SKV_, (long long)SQ_ * D_, 0);
}

// round 5
// speedup vs baseline: 2.7959x; 1.1146x over previous
#include <cuda_runtime.h>
#include <cuda_bf16.h>
#include <math.h>
#include <stdint.h>

#define B_   8
#define SQ_  2048
#define SKV_ 2048
#define D_   1024

typedef __nv_bfloat16 bf16;

// ---------------------------------------------------------------------------
// Device scratch (allocation-free per harness rules)
// ---------------------------------------------------------------------------
__device__ bf16 g_tH [16777216], g_tL [16777216];   // target split
__device__ bf16 g_nH [16777216], g_nL [16777216];   // non_target split
__device__ bf16 g_WqH[ 1048576], g_WqL[ 1048576];
__device__ bf16 g_WkH[ 1048576], g_WkL[ 1048576];
__device__ bf16 g_WvH[ 1048576], g_WvL[ 1048576];
__device__ bf16 g_QH [16777216], g_QL [16777216];
__device__ bf16 g_KH [16777216], g_KL [16777216];
__device__ bf16 g_VtH[16777216], g_VtL[16777216];   // V^T per batch [b][d][kv]
__device__ float g_S [33554432];                    // scores fp32
__device__ bf16 g_PH [33554432], g_PL [33554432];   // probs split

__device__ __forceinline__ uint32_t smem_u32(const void* p) {
    uint32_t a;
    asm("{ .reg .u64 t; cvta.to.shared.u64 t, %1; cvt.u32.u64 %0, t; }" : "=r"(a) : "l"(p));
    return a;
}

// ---------------------------------------------------------------------------
// Warp-MMA primitives (sm_80 baseline; safe under compute_103)
// ---------------------------------------------------------------------------
#define LDSM4(r, ad) \
    asm volatile("ldmatrix.sync.aligned.m8n8.x4.shared.b16 {%0,%1,%2,%3}, [%4];" \
        : "=r"((r)[0]), "=r"((r)[1]), "=r"((r)[2]), "=r"((r)[3]) : "r"(ad))

#define MMA_BF16(c, a, b) \
    asm volatile("mma.sync.aligned.m16n8k16.row.col.f32.bf16.bf16.f32 " \
        "{%0,%1,%2,%3}, {%4,%5,%6,%7}, {%8,%9}, {%0,%1,%2,%3};" \
        : "+f"((c)[0]), "+f"((c)[1]), "+f"((c)[2]), "+f"((c)[3]) \
        : "r"((a)[0]), "r"((a)[1]), "r"((a)[2]), "r"((a)[3]), \
          "r"((b)[0]), "r"((b)[1]))

#define CP_ASYNC16(dst, src) \
    asm volatile("cp.async.cg.shared.global [%0], [%1], 16;" :: "r"(dst), "l"(src))
#define CP_COMMIT()  asm volatile("cp.async.commit_group;" ::: "memory")
#define CP_WAIT1()   asm volatile("cp.async.wait_group 1;" ::: "memory")

// ---------------------------------------------------------------------------
// Split-bf16 NT GEMM: C[m,n] = sum_k (Ah+Al)[m,k]*(Bh+Bl)[n,k] ~= hh+hl+lh (+bias)
// CTA tile 128x128, chunk BK=64 (4 ks-steps), 8 warps (2m x 4n),
// 3-stage cp.async pipeline, register double-buffered fragments.
// EPI: 0 = fp32 C, 1 = split-bf16 + bias, 2 = split-bf16 transposed + bias
// ---------------------------------------------------------------------------
#define STAGES 3
#define ROWB  144                      // 64 bf16 (128B) + 16B pad
#define PLANE (128 * ROWB)             // 18432 B
#define STAGE_BYTES (4 * PLANE)        // 73728 B
#define SMEM_BYTES (STAGES * STAGE_BYTES)  // 221184 B

template <int EPI>
__global__ void __launch_bounds__(256, 1)
mma_nt(const bf16* __restrict__ Ah, const bf16* __restrict__ Al,
       const bf16* __restrict__ Bh, const bf16* __restrict__ Bl,
       void* __restrict__ C0, void* __restrict__ C1,
       const float* __restrict__ bias,
       int K, int ldC,
       long long sA, long long sB, long long sC, int batchRows)
{
    extern __shared__ __align__(128) char smem[];
    const uint32_t sbase = smem_u32(smem);
    const int tid  = threadIdx.x;
    const int lane = tid & 31;
    const int wid  = tid >> 5;
    const int wm   = wid & 1;      // 2 warps along m
    const int wn   = wid >> 1;     // 4 warps along n

    Ah += (long long)blockIdx.z * sA;  Al += (long long)blockIdx.z * sA;
    Bh += (long long)blockIdx.z * sB;  Bl += (long long)blockIdx.z * sB;

    const int m0 = blockIdx.y * 128;
    const int n0 = blockIdx.x * 128;
    const int nChunks = K >> 6;

    // --- cp.async one K-chunk (4 planes x 128 rows x 128B) into a stage ----
    auto issue = [&](int t) {
        if (t < nChunks) {
            const int stage = t % STAGES;
            const int k0 = t << 6;
#pragma unroll
            for (int i = 0; i < 16; ++i) {
                const int idx = tid + (i << 8);       // 0..4095
                const int c = idx & 7;                // 16B chunk within row
                const int r = (idx >> 3) & 127;       // tile row
                const int p = idx >> 10;              // plane
                const bf16* src;
                if      (p == 0) src = Ah + (size_t)(m0 + r) * K + k0 + c * 8;
                else if (p == 1) src = Al + (size_t)(m0 + r) * K + k0 + c * 8;
                else if (p == 2) src = Bh + (size_t)(n0 + r) * K + k0 + c * 8;
                else             src = Bl + (size_t)(n0 + r) * K + k0 + c * 8;
                const uint32_t dst = sbase + stage * STAGE_BYTES + p * PLANE
                                   + r * ROWB + c * 16;
                CP_ASYNC16(dst, src);
            }
        }
        CP_COMMIT();
    };

    float acc[4][4][4];
#pragma unroll
    for (int mi = 0; mi < 4; ++mi)
#pragma unroll
        for (int ni = 0; ni < 4; ++ni)
#pragma unroll
            for (int e = 0; e < 4; ++e) acc[mi][ni][e] = 0.0f;

    // fragment double buffers
    uint32_t ah[2][4][4], al[2][4][4], bh[2][2][4], bl[2][2][4];

    const uint32_t arow = (uint32_t)(wm * 64 + (lane & 15));
    const uint32_t abit = (uint32_t)((lane >> 4) << 4);
    const uint32_t brow = (uint32_t)(wn * 32 + (lane & 7) + ((lane >> 4) << 3));
    const uint32_t bbit = (uint32_t)(((lane >> 3) & 1) << 4);

    auto ldfrag = [&](uint32_t st, int ks, int buf) {
        const uint32_t akoff = (uint32_t)(ks << 5) + abit;   // ks*32B
#pragma unroll
        for (int mi = 0; mi < 4; ++mi) {
            const uint32_t ad = st + (arow + mi * 16) * ROWB + akoff;
            LDSM4(ah[buf][mi], ad);
            LDSM4(al[buf][mi], ad + PLANE);
        }
        const uint32_t bkoff = (uint32_t)(ks << 5) + bbit;
#pragma unroll
        for (int np = 0; np < 2; ++np) {
            const uint32_t bd = st + 2 * PLANE + (brow + np * 16) * ROWB + bkoff;
            LDSM4(bh[buf][np], bd);
            LDSM4(bl[buf][np], bd + PLANE);
        }
    };

    issue(0);
    issue(1);

    for (int t = 0; t < nChunks; ++t) {
        CP_WAIT1();          // chunk t resident; t+1 in flight
        __syncthreads();
        issue(t + 2);        // refill stage freed after iteration t-1

        const uint32_t st = sbase + (t % STAGES) * STAGE_BYTES;
        ldfrag(st, 0, 0);
#pragma unroll
        for (int ks = 0; ks < 4; ++ks) {
            const int cur = ks & 1;
            if (ks < 3) ldfrag(st, ks + 1, cur ^ 1);   // prefetch next ks
#pragma unroll
            for (int mi = 0; mi < 4; ++mi)
#pragma unroll
                for (int ni = 0; ni < 4; ++ni) {
                    const uint32_t* bhp = &bh[cur][ni >> 1][(ni & 1) << 1];
                    const uint32_t* blp = &bl[cur][ni >> 1][(ni & 1) << 1];
                    MMA_BF16(acc[mi][ni], ah[cur][mi], bhp);
                    MMA_BF16(acc[mi][ni], ah[cur][mi], blp);
                    MMA_BF16(acc[mi][ni], al[cur][mi], bhp);
                }
        }
    }

    // ---------------------------- epilogue ---------------------------------
    const int qr = lane >> 2;          // 0..7
    const int qc = (lane & 3) << 1;    // 0,2,4,6

#pragma unroll
    for (int mi = 0; mi < 4; ++mi) {
        const int gm0 = m0 + wm * 64 + mi * 16 + qr;   // row, and gm0+8
#pragma unroll
        for (int ni = 0; ni < 4; ++ni) {
            const int gn = n0 + wn * 32 + ni * 8 + qc;
            float v00 = acc[mi][ni][0], v01 = acc[mi][ni][1];
            float v10 = acc[mi][ni][2], v11 = acc[mi][ni][3];

            if (EPI == 0) {
                float* C = (float*)C0 + (long long)blockIdx.z * sC;
                *reinterpret_cast<float2*>(C + (size_t)gm0 * ldC + gn)
                    = make_float2(v00, v01);
                *reinterpret_cast<float2*>(C + (size_t)(gm0 + 8) * ldC + gn)
                    = make_float2(v10, v11);
            } else {
                const float b0v = bias[gn], b1v = bias[gn + 1];
                v00 += b0v; v01 += b1v; v10 += b0v; v11 += b1v;
                bf16 h00 = __float2bfloat16(v00);
                bf16 h01 = __float2bfloat16(v01);
                bf16 h10 = __float2bfloat16(v10);
                bf16 h11 = __float2bfloat16(v11);
                bf16 l00 = __float2bfloat16(v00 - __bfloat162float(h00));
                bf16 l01 = __float2bfloat16(v01 - __bfloat162float(h01));
                bf16 l10 = __float2bfloat16(v10 - __bfloat162float(h10));
                bf16 l11 = __float2bfloat16(v11 - __bfloat162float(h11));
                bf16* CH = (bf16*)C0;
                bf16* CL = (bf16*)C1;
                if (EPI == 1) {
                    __nv_bfloat162 hp0; hp0.x = h00; hp0.y = h01;
                    __nv_bfloat162 hp1; hp1.x = h10; hp1.y = h11;
                    __nv_bfloat162 lp0; lp0.x = l00; lp0.y = l01;
                    __nv_bfloat162 lp1; lp1.x = l10; lp1.y = l11;
                    *reinterpret_cast<__nv_bfloat162*>(CH + (size_t)gm0 * ldC + gn) = hp0;
                    *reinterpret_cast<__nv_bfloat162*>(CH + (size_t)(gm0 + 8) * ldC + gn) = hp1;
                    *reinterpret_cast<__nv_bfloat162*>(CL + (size_t)gm0 * ldC + gn) = lp0;
                    *reinterpret_cast<__nv_bfloat162*>(CL + (size_t)(gm0 + 8) * ldC + gn) = lp1;
                } else {  // EPI == 2: V^T scatter  (gm -> (bb, s), col-major per batch)
                    const int bb = gm0 / batchRows;
                    const int s0 = gm0 - bb * batchRows;
                    const size_t colbase = ((size_t)bb * ldC + gn) * (size_t)batchRows;
                    CH[colbase + s0]                  = h00;
                    CH[colbase + batchRows + s0]      = h01;
                    CH[colbase + s0 + 8]              = h10;
                    CH[colbase + batchRows + s0 + 8]  = h11;
                    CL[colbase + s0]                  = l00;
                    CL[colbase + batchRows + s0]      = l01;
                    CL[colbase + s0 + 8]              = l10;
                    CL[colbase + batchRows + s0 + 8]  = l11;
                }
            }
        }
    }
}

// ---------------------------------------------------------------------------
// fp32 -> (bf16 hi, bf16 lo), vectorized: 8 elements / thread
// ---------------------------------------------------------------------------
__global__ void split_f32(const float* __restrict__ x, bf16* __restrict__ h,
                          bf16* __restrict__ l, int n)
{
    const int n8 = n >> 3;
    for (int i = blockIdx.x * blockDim.x + threadIdx.x; i < n8; i += gridDim.x * blockDim.x) {
        const float4 a = reinterpret_cast<const float4*>(x)[2 * i];
        const float4 b = reinterpret_cast<const float4*>(x)[2 * i + 1];
        float v[8] = { a.x, a.y, a.z, a.w, b.x, b.y, b.z, b.w };
        __align__(16) bf16 hb[8];
        __align__(16) bf16 lb[8];
#pragma unroll
        for (int j = 0; j < 8; ++j) {
            bf16 hh = __float2bfloat16(v[j]);
            hb[j] = hh;
            lb[j] = __float2bfloat16(v[j] - __bfloat162float(hh));
        }
        reinterpret_cast<uint4*>(h)[i] = *reinterpret_cast<uint4*>(hb);
        reinterpret_cast<uint4*>(l)[i] = *reinterpret_cast<uint4*>(lb);
    }
}

// ---------------------------------------------------------------------------
// Row softmax (2048 cols) fused with split-bf16 conversion; vectorized
// ---------------------------------------------------------------------------
__global__ __launch_bounds__(256)
void softmax_split(const float* __restrict__ S, bf16* __restrict__ Ph, bf16* __restrict__ Pl)
{
    const size_t base = (size_t)blockIdx.x * SKV_;
    const float* p = S + base;
    const int tid = threadIdx.x;
    const int lane = tid & 31;
    const int warp = tid >> 5;
    __shared__ float red[8];

    const float4 a = reinterpret_cast<const float4*>(p)[2 * tid];
    const float4 b = reinterpret_cast<const float4*>(p)[2 * tid + 1];
    float v[8] = { a.x, a.y, a.z, a.w, b.x, b.y, b.z, b.w };

    float m = -INFINITY;
#pragma unroll
    for (int i = 0; i < 8; ++i) m = fmaxf(m, v[i]);
#pragma unroll
    for (int o = 16; o > 0; o >>= 1) m = fmaxf(m, __shfl_xor_sync(0xffffffffu, m, o));
    if (lane == 0) red[warp] = m;
    __syncthreads();
    float mrow = red[0];
#pragma unroll
    for (int w = 1; w < 8; ++w) mrow = fmaxf(mrow, red[w]);
    __syncthreads();

    float s = 0.0f;
#pragma unroll
    for (int i = 0; i < 8; ++i) { v[i] = expf(v[i] - mrow); s += v[i]; }
#pragma unroll
    for (int o = 16; o > 0; o >>= 1) s += __shfl_xor_sync(0xffffffffu, s, o);
    if (lane == 0) red[warp] = s;
    __syncthreads();
    float srow = 0.0f;
#pragma unroll
    for (int w = 0; w < 8; ++w) srow += red[w];
    const float inv = 1.0f / srow;

    __align__(16) bf16 hb[8];
    __align__(16) bf16 lb[8];
#pragma unroll
    for (int i = 0; i < 8; ++i) {
        float pv = v[i] * inv;
        bf16 h = __float2bfloat16(pv);
        hb[i] = h;
        lb[i] = __float2bfloat16(pv - __bfloat162float(h));
    }
    reinterpret_cast<uint4*>(Ph + base)[tid] = *reinterpret_cast<uint4*>(hb);
    reinterpret_cast<uint4*>(Pl + base)[tid] = *reinterpret_cast<uint4*>(lb);
}

// ---------------------------------------------------------------------------
// Launch
// ---------------------------------------------------------------------------
extern "C" void kernel_launch(void* const* d_in, const int* in_sizes, int n_in,
                              void* d_out, int out_size)
{
    const float* target     = (const float*)d_in[0];
    const float* non_target = (const float*)d_in[1];
    const float* Wq = (const float*)d_in[2];
    const float* bq = (const float*)d_in[3];
    const float* Wk = (const float*)d_in[4];
    const float* bk = (const float*)d_in[5];
    const float* Wv = (const float*)d_in[6];
    const float* bv = (const float*)d_in[7];
    float* out = (float*)d_out;

    bf16 *tH, *tL, *nH, *nL, *WqH, *WqL, *WkH, *WkL, *WvH, *WvL;
    bf16 *QH, *QL, *KH, *KL, *VtH, *VtL, *PH, *PL;
    float* S;
    cudaGetSymbolAddress((void**)&tH,  g_tH);  cudaGetSymbolAddress((void**)&tL,  g_tL);
    cudaGetSymbolAddress((void**)&nH,  g_nH);  cudaGetSymbolAddress((void**)&nL,  g_nL);
    cudaGetSymbolAddress((void**)&WqH, g_WqH); cudaGetSymbolAddress((void**)&WqL, g_WqL);
    cudaGetSymbolAddress((void**)&WkH, g_WkH); cudaGetSymbolAddress((void**)&WkL, g_WkL);
    cudaGetSymbolAddress((void**)&WvH, g_WvH); cudaGetSymbolAddress((void**)&WvL, g_WvL);
    cudaGetSymbolAddress((void**)&QH,  g_QH);  cudaGetSymbolAddress((void**)&QL,  g_QL);
    cudaGetSymbolAddress((void**)&KH,  g_KH);  cudaGetSymbolAddress((void**)&KL,  g_KL);
    cudaGetSymbolAddress((void**)&VtH, g_VtH); cudaGetSymbolAddress((void**)&VtL, g_VtL);
    cudaGetSymbolAddress((void**)&PH,  g_PH);  cudaGetSymbolAddress((void**)&PL,  g_PL);
    cudaGetSymbolAddress((void**)&S,   g_S);

    cudaFuncSetAttribute(mma_nt<0>, cudaFuncAttributeMaxDynamicSharedMemorySize, SMEM_BYTES);
    cudaFuncSetAttribute(mma_nt<1>, cudaFuncAttributeMaxDynamicSharedMemorySize, SMEM_BYTES);
    cudaFuncSetAttribute(mma_nt<2>, cudaFuncAttributeMaxDynamicSharedMemorySize, SMEM_BYTES);

    const dim3 blk(256);

    // input conversions (8 elems/thread, exact cover)
    split_f32<<<8192, blk>>>(target,     tH, tL, B_ * SQ_ * D_);
    split_f32<<<8192, blk>>>(non_target, nH, nL, B_ * SKV_ * D_);
    split_f32<<<512,  blk>>>(Wq, WqH, WqL, D_ * D_);
    split_f32<<<512,  blk>>>(Wk, WkH, WkL, D_ * D_);
    split_f32<<<512,  blk>>>(Wv, WvH, WvL, D_ * D_);

    // Q/K/V projections (M = B*S folded, N = D, K = D)
    mma_nt<1><<<dim3(8, 128, 1), blk, SMEM_BYTES>>>(
        tH, tL, WqH, WqL, QH, QL, bq, D_, D_, 0, 0, 0, 0);
    mma_nt<1><<<dim3(8, 128, 1), blk, SMEM_BYTES>>>(
        nH, nL, WkH, WkL, KH, KL, bk, D_, D_, 0, 0, 0, 0);
    mma_nt<2><<<dim3(8, 128, 1), blk, SMEM_BYTES>>>(
        nH, nL, WvH, WvL, VtH, VtL, bv, D_, D_, 0, 0, 0, SKV_);

    // S[b] = Q[b] @ K[b]^T
    mma_nt<0><<<dim3(16, 16, 8), blk, SMEM_BYTES>>>(
        QH, QL, KH, KL, S, nullptr, nullptr, D_, SKV_,
        (long long)SQ_ * D_, (long long)SKV_ * D_, (long long)SQ_ * SKV_, 0);

    // softmax + split conversion of P
    softmax_split<<<B_ * SQ_, blk>>>(S, PH, PL);

    // O[b] = P[b] @ Vt[b]^T
    mma_nt<0><<<dim3(8, 16, 8), blk, SMEM_BYTES>>>(
        PH, PL, VtH, VtL, out, nullptr, nullptr, SKV_, D_,
        (long long)SQ_ * SKV_, (long long)D_ * SKV_, (long long)SQ_ * D_, 0);
}